// round 5
// baseline (speedup 1.0000x reference)
#include <cuda_runtime.h>

// ---------------------------------------------------------------------------
// Problem constants: B=4, S=2048, C=1024, H=16, D=64
// ---------------------------------------------------------------------------
#define S_   2048
#define C_   1024
#define H_   16
#define D_   64
#define M_   8192           // B*S rows

// Scratch (static device globals; allocation-free per harness rules)
__device__ float g_qkv[(size_t)M_ * 3 * C_];            // 96 MB: (B,S,3,H,D)
__device__ float g_ropeT[(size_t)64 * 2 * D_ * S_];     // 64 MB: [bh][t][d][s]
__device__ float g_attn[(size_t)M_ * C_];               // 32 MB: (B,S,C)

// ---------------------------------------------------------------------------
// f32x2 packed helpers (Blackwell dual fp32 path — only reachable via PTX)
// ---------------------------------------------------------------------------
__device__ __forceinline__ unsigned long long pack2(float lo, float hi) {
    unsigned long long r;
    asm("mov.b64 %0, {%1, %2};" : "=l"(r) : "f"(lo), "f"(hi));
    return r;
}
__device__ __forceinline__ void unpack2(unsigned long long v, float& lo, float& hi) {
    asm("mov.b64 {%0, %1}, %2;" : "=f"(lo), "=f"(hi) : "l"(v));
}
__device__ __forceinline__ unsigned long long ffma2(unsigned long long a,
                                                    unsigned long long b,
                                                    unsigned long long c) {
    unsigned long long d;
    asm("fma.rn.f32x2 %0, %1, %2, %3;" : "=l"(d) : "l"(a), "l"(b), "l"(c));
    return d;
}
__device__ __forceinline__ unsigned long long fmul2(unsigned long long a,
                                                    unsigned long long b) {
    unsigned long long d;
    asm("mul.rn.f32x2 %0, %1, %2;" : "=l"(d) : "l"(a), "l"(b));
    return d;
}

// ---------------------------------------------------------------------------
// GEMM: C[m][n] = sum_k A[m][k]*W[n][k] + bias[n]
// A: M x K row-major, W: N x K row-major. 128x128x8 tiles, 256 threads,
// 8x8 per-thread tile (split columns tx*4 and 64+tx*4), double-buffered smem.
// ---------------------------------------------------------------------------
__global__ __launch_bounds__(256, 2)
void gemm_nt_bias(const float* __restrict__ A, const float* __restrict__ W,
                  const float* __restrict__ bias, float* __restrict__ Cout,
                  int N, int K)
{
    __shared__ float As[2][8][132];
    __shared__ float Bs[2][8][132];

    const int tid  = threadIdx.x;
    const int tx   = tid & 15;
    const int ty   = tid >> 4;
    const int lrow = tid >> 1;          // 0..127
    const int lk4  = (tid & 1) * 4;     // 0 or 4

    const int m0 = blockIdx.y * 128;
    const int n0 = blockIdx.x * 128;

    const float* Ap = A + (size_t)(m0 + lrow) * K + lk4;
    const float* Wp = W + (size_t)(n0 + lrow) * K + lk4;

    // prologue: stage tile 0 (transposed; STS pattern is conflict-free)
    {
        float4 av = *(const float4*)Ap;
        float4 wv = *(const float4*)Wp;
        As[0][lk4 + 0][lrow] = av.x; As[0][lk4 + 1][lrow] = av.y;
        As[0][lk4 + 2][lrow] = av.z; As[0][lk4 + 3][lrow] = av.w;
        Bs[0][lk4 + 0][lrow] = wv.x; Bs[0][lk4 + 1][lrow] = wv.y;
        Bs[0][lk4 + 2][lrow] = wv.z; Bs[0][lk4 + 3][lrow] = wv.w;
    }
    __syncthreads();

    unsigned long long acc[8][4];
#pragma unroll
    for (int i = 0; i < 8; ++i) {
        acc[i][0] = 0ull; acc[i][1] = 0ull; acc[i][2] = 0ull; acc[i][3] = 0ull;
    }

    const int nk = K >> 3;
    for (int kt = 0; kt < nk; ++kt) {
        const int buf = kt & 1;
        float4 avn, wvn;
        const bool has_next = (kt + 1 < nk);
        if (has_next) {
            avn = *(const float4*)(Ap + (size_t)(kt + 1) * 8);
            wvn = *(const float4*)(Wp + (size_t)(kt + 1) * 8);
        }
#pragma unroll
        for (int k = 0; k < 8; ++k) {
            float4 a0 = *(const float4*)&As[buf][k][ty * 8];
            float4 a1 = *(const float4*)&As[buf][k][ty * 8 + 4];
            float4 bf0 = *(const float4*)&Bs[buf][k][tx * 4];
            float4 bf1 = *(const float4*)&Bs[buf][k][64 + tx * 4];
            unsigned long long b0 = pack2(bf0.x, bf0.y);
            unsigned long long b1 = pack2(bf0.z, bf0.w);
            unsigned long long b2 = pack2(bf1.x, bf1.y);
            unsigned long long b3 = pack2(bf1.z, bf1.w);
            float a[8] = {a0.x, a0.y, a0.z, a0.w, a1.x, a1.y, a1.z, a1.w};
#pragma unroll
            for (int i = 0; i < 8; ++i) {
                unsigned long long apk = pack2(a[i], a[i]);
                acc[i][0] = ffma2(apk, b0, acc[i][0]);
                acc[i][1] = ffma2(apk, b1, acc[i][1]);
                acc[i][2] = ffma2(apk, b2, acc[i][2]);
                acc[i][3] = ffma2(apk, b3, acc[i][3]);
            }
        }
        if (has_next) {
            const int nb = buf ^ 1;
            As[nb][lk4 + 0][lrow] = avn.x; As[nb][lk4 + 1][lrow] = avn.y;
            As[nb][lk4 + 2][lrow] = avn.z; As[nb][lk4 + 3][lrow] = avn.w;
            Bs[nb][lk4 + 0][lrow] = wvn.x; Bs[nb][lk4 + 1][lrow] = wvn.y;
            Bs[nb][lk4 + 2][lrow] = wvn.z; Bs[nb][lk4 + 3][lrow] = wvn.w;
            __syncthreads();
        }
    }

    // epilogue: bias + store (split columns)
    float4 bb0 = *(const float4*)&bias[n0 + tx * 4];
    float4 bb1 = *(const float4*)&bias[n0 + 64 + tx * 4];
#pragma unroll
    for (int i = 0; i < 8; ++i) {
        float c0, c1, c2, c3, c4, c5, c6, c7;
        unpack2(acc[i][0], c0, c1);
        unpack2(acc[i][1], c2, c3);
        unpack2(acc[i][2], c4, c5);
        unpack2(acc[i][3], c6, c7);
        float* cp = Cout + (size_t)(m0 + ty * 8 + i) * N + n0;
        *(float4*)(cp + tx * 4) =
            make_float4(c0 + bb0.x, c1 + bb0.y, c2 + bb0.z, c3 + bb0.w);
        *(float4*)(cp + 64 + tx * 4) =
            make_float4(c4 + bb1.x, c5 + bb1.y, c6 + bb1.z, c7 + bb1.w);
    }
}

// ---------------------------------------------------------------------------
// RoPE + transpose: reads q (t=0) / k (t=1) from g_qkv, applies rotary embed,
// writes d-major layout g_ropeT[(bh*2+t)][d][s] for coalesced flash staging.
// Grid: (S/64, B*H, 2), 256 threads. Dynamic smem: 3 tiles [64][67].
// ---------------------------------------------------------------------------
__global__ __launch_bounds__(256)
void rope_t_kernel(const float* __restrict__ qkv,
                   const float* __restrict__ cosp,
                   const float* __restrict__ sinp,
                   float* __restrict__ ropeT)
{
    extern __shared__ float rs[];
    float* Tx = rs;                 // [64][67] x
    float* Tc = rs + 64 * 67;       // cos
    float* Ts = rs + 2 * 64 * 67;   // sin

    const int tid = threadIdx.x;
    const int s0  = blockIdx.x * 64;
    const int bh  = blockIdx.y;
    const int b   = bh >> 4;
    const int h   = bh & 15;
    const int t   = blockIdx.z;

#pragma unroll
    for (int it = 0; it < 4; ++it) {
        int idx = it * 256 + tid;        // 0..1023
        int sl  = idx >> 4;              // 0..63
        int dc  = (idx & 15) * 4;        // 0..60
        size_t bs = (size_t)(b * S_ + s0 + sl);
        float4 xv = *(const float4*)(qkv + (bs * 3 + t) * C_ + h * D_ + dc);
        float4 cv = *(const float4*)(cosp + bs * D_ + dc);
        float4 sv = *(const float4*)(sinp + bs * D_ + dc);
        Tx[sl * 67 + dc + 0] = xv.x; Tx[sl * 67 + dc + 1] = xv.y;
        Tx[sl * 67 + dc + 2] = xv.z; Tx[sl * 67 + dc + 3] = xv.w;
        Tc[sl * 67 + dc + 0] = cv.x; Tc[sl * 67 + dc + 1] = cv.y;
        Tc[sl * 67 + dc + 2] = cv.z; Tc[sl * 67 + dc + 3] = cv.w;
        Ts[sl * 67 + dc + 0] = sv.x; Ts[sl * 67 + dc + 1] = sv.y;
        Ts[sl * 67 + dc + 2] = sv.z; Ts[sl * 67 + dc + 3] = sv.w;
    }
    __syncthreads();

#pragma unroll
    for (int it = 0; it < 4; ++it) {
        int idx = it * 256 + tid;
        int d   = idx >> 4;              // 0..63
        int sc  = (idx & 15) * 4;        // 0..60
        float out[4];
#pragma unroll
        for (int j = 0; j < 4; ++j) {
            int sl = sc + j;
            float x0 = Tx[sl * 67 + d];
            float x1 = Tx[sl * 67 + (d ^ 32)];
            float c  = Tc[sl * 67 + d];
            float sn = Ts[sl * 67 + d];
            float rh = (d < 32) ? -x1 : x1;
            out[j] = fmaf(x0, c, rh * sn);
        }
        *(float4*)(ropeT + ((size_t)(bh * 2 + t) * D_ + d) * S_ + s0 + sc) =
            make_float4(out[0], out[1], out[2], out[3]);
    }
}

// ---------------------------------------------------------------------------
// Flash attention fp32. Grid (S/128, B*H), 256 threads, 1 CTA per q-block.
// smem: QT[64][132], KT[64][132] (d-major), Vs[128][68], Ps[128][132].
// Thread tile: scores 8 rows (ty*8+i) x 8 keys (split: tx*4, 64+tx*4);
// output 8 rows x 4 dims (tx*4). Row reductions via shfl.xor (bits 0-3).
// ---------------------------------------------------------------------------
#define FLASH_SMEM_FLOATS (64*132 + 64*132 + 128*68 + 128*132)
#define FLASH_SMEM_BYTES  (FLASH_SMEM_FLOATS * 4)

__global__ __launch_bounds__(256, 1)
void flash_kernel(const float* __restrict__ ropeT,
                  const float* __restrict__ qkv,
                  float* __restrict__ attn)
{
    extern __shared__ float sm[];
    float* QT = sm;                       // [64][132]
    float* KT = sm + 64 * 132;            // [64][132]
    float* Vs = sm + 2 * 64 * 132;        // [128][68]
    float* Ps = sm + 2 * 64 * 132 + 128 * 68; // [128][132]

    const int tid = threadIdx.x;
    const int tx  = tid & 15;
    const int ty  = tid >> 4;
    const int qb  = blockIdx.x;           // 0..15
    const int bh  = blockIdx.y;           // 0..63
    const int b   = bh >> 4;
    const int h   = bh & 15;
    const int q0  = qb * 128;

    // stage QT (coalesced: ropeT is d-major)
    const float* qsrc = ropeT + (size_t)(bh * 2 + 0) * D_ * S_;
#pragma unroll
    for (int it = 0; it < 8; ++it) {
        int idx = it * 256 + tid;        // 0..2047
        int d   = idx >> 5;              // 0..63
        int sc  = (idx & 31) * 4;        // 0..124
        float4 v = *(const float4*)(qsrc + (size_t)d * S_ + q0 + sc);
        *(float4*)&QT[d * 132 + sc] = v;
    }

    float m_i[8], l_i[8];
    unsigned long long o[8][2];
#pragma unroll
    for (int i = 0; i < 8; ++i) {
        m_i[i] = -1.0e30f; l_i[i] = 0.0f;
        o[i][0] = 0ull; o[i][1] = 0ull;
    }

    const float* ksrc = ropeT + (size_t)(bh * 2 + 1) * D_ * S_;

    for (int kb = 0; kb < 16; ++kb) {
        __syncthreads();   // previous PV readers done; also covers QT on kb=0
        const int k0 = kb * 128;

        // stage KT (d-major gmem -> conflict-free float4 STS)
#pragma unroll
        for (int it = 0; it < 8; ++it) {
            int idx = it * 256 + tid;
            int d   = idx >> 5;
            int sc  = (idx & 31) * 4;
            float4 v = *(const float4*)(ksrc + (size_t)d * S_ + k0 + sc);
            *(float4*)&KT[d * 132 + sc] = v;
        }
        // stage Vs (row-major from g_qkv, t=2)
#pragma unroll
        for (int it = 0; it < 8; ++it) {
            int idx = it * 256 + tid;
            int sl  = idx >> 4;           // 0..127
            int dc  = (idx & 15) * 4;     // 0..60
            float4 v = *(const float4*)(qkv +
                ((size_t)(b * S_ + k0 + sl) * 3 + 2) * C_ + h * D_ + dc);
            *(float4*)&Vs[sl * 68 + dc] = v;
        }
        __syncthreads();

        // ---- S = Q @ K^T (128x128 tile, f32x2 over adjacent keys) ----
        unsigned long long acc[8][4];
#pragma unroll
        for (int i = 0; i < 8; ++i) {
            acc[i][0] = 0ull; acc[i][1] = 0ull;
            acc[i][2] = 0ull; acc[i][3] = 0ull;
        }
#pragma unroll 4
        for (int d = 0; d < 64; ++d) {
            float4 qa = *(const float4*)&QT[d * 132 + ty * 8];
            float4 qc = *(const float4*)&QT[d * 132 + ty * 8 + 4];
            float4 k0f = *(const float4*)&KT[d * 132 + tx * 4];
            float4 k1f = *(const float4*)&KT[d * 132 + 64 + tx * 4];
            unsigned long long kk0 = pack2(k0f.x, k0f.y);
            unsigned long long kk1 = pack2(k0f.z, k0f.w);
            unsigned long long kk2 = pack2(k1f.x, k1f.y);
            unsigned long long kk3 = pack2(k1f.z, k1f.w);
            float qs[8] = {qa.x, qa.y, qa.z, qa.w, qc.x, qc.y, qc.z, qc.w};
#pragma unroll
            for (int i = 0; i < 8; ++i) {
                unsigned long long qq = pack2(qs[i], qs[i]);
                acc[i][0] = ffma2(qq, kk0, acc[i][0]);
                acc[i][1] = ffma2(qq, kk1, acc[i][1]);
                acc[i][2] = ffma2(qq, kk2, acc[i][2]);
                acc[i][3] = ffma2(qq, kk3, acc[i][3]);
            }
        }

        // ---- online softmax (per thread: 8 rows x 8 keys) ----
#pragma unroll
        for (int i = 0; i < 8; ++i) {
            float s0, s1, s2, s3, s4, s5, s6, s7;
            unpack2(acc[i][0], s0, s1);
            unpack2(acc[i][1], s2, s3);
            unpack2(acc[i][2], s4, s5);
            unpack2(acc[i][3], s6, s7);
            const float sc = 0.125f;  // D^-0.5
            s0 *= sc; s1 *= sc; s2 *= sc; s3 *= sc;
            s4 *= sc; s5 *= sc; s6 *= sc; s7 *= sc;
            float mx = fmaxf(fmaxf(fmaxf(s0, s1), fmaxf(s2, s3)),
                             fmaxf(fmaxf(s4, s5), fmaxf(s6, s7)));
#pragma unroll
            for (int off = 1; off < 16; off <<= 1)
                mx = fmaxf(mx, __shfl_xor_sync(0xffffffffu, mx, off));
            float mnew  = fmaxf(m_i[i], mx);
            float alpha = __expf(m_i[i] - mnew);
            m_i[i] = mnew;
            float p0 = __expf(s0 - mnew), p1 = __expf(s1 - mnew);
            float p2 = __expf(s2 - mnew), p3 = __expf(s3 - mnew);
            float p4 = __expf(s4 - mnew), p5 = __expf(s5 - mnew);
            float p6 = __expf(s6 - mnew), p7 = __expf(s7 - mnew);
            float lsum = ((p0 + p1) + (p2 + p3)) + ((p4 + p5) + (p6 + p7));
#pragma unroll
            for (int off = 1; off < 16; off <<= 1)
                lsum += __shfl_xor_sync(0xffffffffu, lsum, off);
            l_i[i] = l_i[i] * alpha + lsum;
            unsigned long long a2 = pack2(alpha, alpha);
            o[i][0] = fmul2(o[i][0], a2);
            o[i][1] = fmul2(o[i][1], a2);
            int r = ty * 8 + i;
            *(float4*)&Ps[r * 132 + tx * 4]      = make_float4(p0, p1, p2, p3);
            *(float4*)&Ps[r * 132 + 64 + tx * 4] = make_float4(p4, p5, p6, p7);
        }
        __syncthreads();

        // ---- O += P @ V (thread: 8 rows x 4 dims, f32x2 over dims) ----
#pragma unroll 2
        for (int kc = 0; kc < 128; kc += 4) {
            unsigned long long vv[4][2];
#pragma unroll
            for (int kk = 0; kk < 4; ++kk) {
                float4 v = *(const float4*)&Vs[(kc + kk) * 68 + tx * 4];
                vv[kk][0] = pack2(v.x, v.y);
                vv[kk][1] = pack2(v.z, v.w);
            }
#pragma unroll
            for (int i = 0; i < 8; ++i) {
                float4 pf = *(const float4*)&Ps[(ty * 8 + i) * 132 + kc];
                unsigned long long px = pack2(pf.x, pf.x);
                unsigned long long py = pack2(pf.y, pf.y);
                unsigned long long pz = pack2(pf.z, pf.z);
                unsigned long long pw = pack2(pf.w, pf.w);
                o[i][0] = ffma2(px, vv[0][0], o[i][0]);
                o[i][1] = ffma2(px, vv[0][1], o[i][1]);
                o[i][0] = ffma2(py, vv[1][0], o[i][0]);
                o[i][1] = ffma2(py, vv[1][1], o[i][1]);
                o[i][0] = ffma2(pz, vv[2][0], o[i][0]);
                o[i][1] = ffma2(pz, vv[2][1], o[i][1]);
                o[i][0] = ffma2(pw, vv[3][0], o[i][0]);
                o[i][1] = ffma2(pw, vv[3][1], o[i][1]);
            }
        }
    }

    // ---- normalize + store ----
#pragma unroll
    for (int i = 0; i < 8; ++i) {
        float inv = 1.0f / l_i[i];
        float o0, o1, o2, o3;
        unpack2(o[i][0], o0, o1);
        unpack2(o[i][1], o2, o3);
        size_t row = (size_t)(b * S_ + q0 + ty * 8 + i);
        *(float4*)&attn[row * C_ + h * D_ + tx * 4] =
            make_float4(o0 * inv, o1 * inv, o2 * inv, o3 * inv);
    }
}

// ---------------------------------------------------------------------------
// Launch
// ---------------------------------------------------------------------------
extern "C" void kernel_launch(void* const* d_in, const int* in_sizes, int n_in,
                              void* d_out, int out_size)
{
    (void)in_sizes; (void)n_in; (void)out_size;
    const float* hidden = (const float*)d_in[0];
    const float* cosp   = (const float*)d_in[1];
    const float* sinp   = (const float*)d_in[2];
    const float* qkv_w  = (const float*)d_in[3];
    const float* qkv_b  = (const float*)d_in[4];
    const float* proj_w = (const float*)d_in[5];
    const float* proj_b = (const float*)d_in[6];
    float* out = (float*)d_out;

    float *qkv_s = nullptr, *ropeT_s = nullptr, *attn_s = nullptr;
    cudaGetSymbolAddress((void**)&qkv_s,   g_qkv);
    cudaGetSymbolAddress((void**)&ropeT_s, g_ropeT);
    cudaGetSymbolAddress((void**)&attn_s,  g_attn);

    const int rope_smem = 3 * 64 * 67 * 4;  // 51456
    cudaFuncSetAttribute(rope_t_kernel,
                         cudaFuncAttributeMaxDynamicSharedMemorySize, rope_smem);
    cudaFuncSetAttribute(flash_kernel,
                         cudaFuncAttributeMaxDynamicSharedMemorySize, FLASH_SMEM_BYTES);

    // 1) QKV GEMM: (8192,1024) @ (3072,1024)^T + b -> g_qkv
    gemm_nt_bias<<<dim3(3 * C_ / 128, M_ / 128), 256>>>(
        hidden, qkv_w, qkv_b, qkv_s, 3 * C_, C_);

    // 2) RoPE + transpose q,k -> g_ropeT [bh][t][d][s]
    rope_t_kernel<<<dim3(S_ / 64, 64, 2), 256, rope_smem>>>(
        qkv_s, cosp, sinp, ropeT_s);

    // 3) Flash attention -> g_attn
    flash_kernel<<<dim3(S_ / 128, 64), 256, FLASH_SMEM_BYTES>>>(
        ropeT_s, qkv_s, attn_s);

    // 4) Proj GEMM: (8192,1024) @ (1024,1024)^T + b -> out
    gemm_nt_bias<<<dim3(C_ / 128, M_ / 128), 256>>>(
        attn_s, proj_w, proj_b, out, C_, C_);
}